// round 1
// baseline (speedup 1.0000x reference)
#include <cuda_runtime.h>

// 2x2 non-overlapping max pool, fp32.
// Input : (16, 64, 512, 512) flattened as (IMG=1024, 512, 512)
// Output: (16, 64, 256, 256) flattened as (IMG=1024, 256, 256)
//
// Each thread produces one float4 of output (4 output columns), reading
// 2 x float4 from each of the two contributing input rows. Fully coalesced
// 128B transactions on load and store. Pure HBM-streaming kernel.

#define IMG   1024      // 16 * 64
#define H     512
#define W     512
#define OH    256
#define OW    256

// float4 outputs per output row: OW / 4 = 64
#define OV_PER_ROW 64
// total float4 outputs: IMG * OH * OV_PER_ROW = 1024 * 256 * 64 = 16,777,216
#define TOTAL_V4   (IMG * OH * OV_PER_ROW)

__global__ __launch_bounds__(256) void maxpool2x2_kernel(
    const float* __restrict__ in, float* __restrict__ out)
{
    int t = blockIdx.x * blockDim.x + threadIdx.x;   // < TOTAL_V4 (exact grid)

    // Decompose: t = ((img * OH) + orow) * OV_PER_ROW + ovec
    int ovec = t & (OV_PER_ROW - 1);        // 0..63
    int rest = t >> 6;                      // img*OH + orow
    int orow = rest & (OH - 1);             // 0..255
    int img  = rest >> 8;                   // 0..1023

    // Input base: two rows (2*orow, 2*orow+1), 8 input cols starting at 8*ovec
    const float4* r0 = (const float4*)(in + (size_t)img * (H * W) + (size_t)(2 * orow) * W + 8 * ovec);
    const float4* r1 = (const float4*)((const float*)r0 + W);

    // Front-batched loads (MLP=4)
    float4 a0 = r0[0];
    float4 a1 = r0[1];
    float4 b0 = r1[0];
    float4 b1 = r1[1];

    float4 o;
    o.x = fmaxf(fmaxf(a0.x, a0.y), fmaxf(b0.x, b0.y));
    o.y = fmaxf(fmaxf(a0.z, a0.w), fmaxf(b0.z, b0.w));
    o.z = fmaxf(fmaxf(a1.x, a1.y), fmaxf(b1.x, b1.y));
    o.w = fmaxf(fmaxf(a1.z, a1.w), fmaxf(b1.z, b1.w));

    ((float4*)(out + (size_t)img * (OH * OW) + (size_t)orow * OW + 4 * ovec))[0] = o;
}

extern "C" void kernel_launch(void* const* d_in, const int* in_sizes, int n_in,
                              void* d_out, int out_size)
{
    const float* in  = (const float*)d_in[0];
    float*       out = (float*)d_out;

    // TOTAL_V4 = 16,777,216 threads; 256 threads/block -> 65,536 blocks (exact)
    maxpool2x2_kernel<<<TOTAL_V4 / 256, 256>>>(in, out);
}